// round 2
// baseline (speedup 1.0000x reference)
#include <cuda_runtime.h>

#define HW_ (128*128)
#define NTOT (16*64)

__device__ float g_Q[NTOT * HW_];
__device__ float g_V[NTOT * HW_];
__device__ float g_K[NTOT * HW_];

// ---- packed fp32x2 helpers (Blackwell FFMA2 path; ptxas never emits these) ----
__device__ __forceinline__ unsigned long long pack2(float lo, float hi) {
    unsigned long long r;
    asm("mov.b64 %0, {%1, %2};" : "=l"(r) : "f"(lo), "f"(hi));
    return r;
}
__device__ __forceinline__ void unpack2(unsigned long long v, float& lo, float& hi) {
    asm("mov.b64 {%0, %1}, %2;" : "=f"(lo), "=f"(hi) : "l"(v));
}
__device__ __forceinline__ unsigned long long fma2(unsigned long long a,
                                                   unsigned long long b,
                                                   unsigned long long c) {
    unsigned long long d;
    asm("fma.rn.f32x2 %0, %1, %2, %3;" : "=l"(d) : "l"(a), "l"(b), "l"(c));
    return d;
}

// ---------------------------------------------------------------------------
// Kernel 1: fused 1x1-conv projections (Q from e, V/K from x), f32x2 math.
// ---------------------------------------------------------------------------
__global__ __launch_bounds__(256) void qvk_kernel(
    const float* __restrict__ x, const float* __restrict__ e,
    const float* __restrict__ W1, const float* __restrict__ b1,
    const float* __restrict__ W2, const float* __restrict__ b2,
    const float* __restrict__ W3, const float* __restrict__ b3)
{
    extern __shared__ float sm[];
    float* Xs  = sm;               // [64][128]
    float* Es  = Xs + 64*128;      // [16][128]
    float* W2s = Es + 16*128;      // [64][68]
    float* W3s = W2s + 64*68;
    float* W1s = W3s + 64*68;      // [16][68]
    float* b1s = W1s + 16*68;
    float* b2s = b1s + 64;
    float* b3s = b2s + 64;

    const int tid = threadIdx.x;
    const int b   = blockIdx.y;
    const int p0  = blockIdx.x * 128;

    for (int idx = tid; idx < 4096; idx += 256) {
        int o = idx >> 6, c = idx & 63;
        W2s[c*68 + o] = W2[idx];
        W3s[c*68 + o] = W3[idx];
    }
    for (int idx = tid; idx < 1024; idx += 256) {
        int o = idx >> 4, c = idx & 15;
        W1s[c*68 + o] = W1[idx];
    }
    if (tid < 64) { b1s[tid] = b1[tid]; b2s[tid] = b2[tid]; b3s[tid] = b3[tid]; }

    for (int idx = tid; idx < 64*128; idx += 256) {
        int c = idx >> 7, p = idx & 127;
        Xs[idx] = x[(b*64 + c)*HW_ + p0 + p];
    }
    for (int idx = tid; idx < 16*128; idx += 256) {
        int c = idx >> 7, p = idx & 127;
        Es[idx] = e[(b*16 + c)*HW_ + p0 + p];
    }
    __syncthreads();

    const int oi = tid >> 4;
    const int pj = tid & 15;

    // acc[i][jp] : output channel oi*4+i, pixel pair pj*8 + 2*jp{,+1}
    unsigned long long accQ[4][4], accV[4][4], accK[4][4];
    #pragma unroll
    for (int i = 0; i < 4; i++) {
        unsigned long long bq = pack2(b1s[oi*4+i], b1s[oi*4+i]);
        unsigned long long bv = pack2(b2s[oi*4+i], b2s[oi*4+i]);
        unsigned long long bk = pack2(b3s[oi*4+i], b3s[oi*4+i]);
        #pragma unroll
        for (int j = 0; j < 4; j++) { accQ[i][j] = bq; accV[i][j] = bv; accK[i][j] = bk; }
    }

    #pragma unroll 4
    for (int c = 0; c < 64; c++) {
        float4 a2v = *(const float4*)&W2s[c*68 + oi*4];
        float4 a3v = *(const float4*)&W3s[c*68 + oi*4];
        ulonglong2 x01 = *(const ulonglong2*)&Xs[c*128 + pj*8];
        ulonglong2 x23 = *(const ulonglong2*)&Xs[c*128 + pj*8 + 4];
        unsigned long long xv[4] = {x01.x, x01.y, x23.x, x23.y};
        unsigned long long p2[4] = {pack2(a2v.x,a2v.x), pack2(a2v.y,a2v.y),
                                    pack2(a2v.z,a2v.z), pack2(a2v.w,a2v.w)};
        unsigned long long p3[4] = {pack2(a3v.x,a3v.x), pack2(a3v.y,a3v.y),
                                    pack2(a3v.z,a3v.z), pack2(a3v.w,a3v.w)};
        #pragma unroll
        for (int i = 0; i < 4; i++)
            #pragma unroll
            for (int j = 0; j < 4; j++) {
                accV[i][j] = fma2(p2[i], xv[j], accV[i][j]);
                accK[i][j] = fma2(p3[i], xv[j], accK[i][j]);
            }
    }
    #pragma unroll 4
    for (int c = 0; c < 16; c++) {
        float4 a1v = *(const float4*)&W1s[c*68 + oi*4];
        ulonglong2 e01 = *(const ulonglong2*)&Es[c*128 + pj*8];
        ulonglong2 e23 = *(const ulonglong2*)&Es[c*128 + pj*8 + 4];
        unsigned long long ev[4] = {e01.x, e01.y, e23.x, e23.y};
        unsigned long long p1[4] = {pack2(a1v.x,a1v.x), pack2(a1v.y,a1v.y),
                                    pack2(a1v.z,a1v.z), pack2(a1v.w,a1v.w)};
        #pragma unroll
        for (int i = 0; i < 4; i++)
            #pragma unroll
            for (int j = 0; j < 4; j++)
                accQ[i][j] = fma2(p1[i], ev[j], accQ[i][j]);
    }

    #pragma unroll
    for (int i = 0; i < 4; i++) {
        int o  = oi*4 + i;
        int gb = (b*64 + o)*HW_ + p0 + pj*8;
        ulonglong2 q01 = make_ulonglong2(accQ[i][0], accQ[i][1]);
        ulonglong2 q23 = make_ulonglong2(accQ[i][2], accQ[i][3]);
        ulonglong2 v01 = make_ulonglong2(accV[i][0], accV[i][1]);
        ulonglong2 v23 = make_ulonglong2(accV[i][2], accV[i][3]);
        ulonglong2 k01 = make_ulonglong2(accK[i][0], accK[i][1]);
        ulonglong2 k23 = make_ulonglong2(accK[i][2], accK[i][3]);
        *(ulonglong2*)&g_Q[gb]     = q01;
        *(ulonglong2*)&g_Q[gb + 4] = q23;
        *(ulonglong2*)&g_V[gb]     = v01;
        *(ulonglong2*)&g_V[gb + 4] = v23;
        *(ulonglong2*)&g_K[gb]     = k01;
        *(ulonglong2*)&g_K[gb + 4] = k23;
    }
}

// ---------------------------------------------------------------------------
// Kernel 2: per-head attention, f32x2 math.
// ---------------------------------------------------------------------------
#define LDP 132

__global__ __launch_bounds__(256) void attn_kernel(float* __restrict__ out)
{
    extern __shared__ float sm[];
    float* A  = sm;              // Q^T[w][h] -> later P[h][g]
    float* Bm = sm + 128*LDP;    // V^T[w][g] -> later K[g][w]

    const int tid = threadIdx.x;
    const int n   = blockIdx.x;
    const float* Q = g_Q + n*HW_;
    const float* V = g_V + n*HW_;
    const float* K = g_K + n*HW_;

    for (int idx = tid; idx < HW_; idx += 256) {
        int r = idx >> 7, w = idx & 127;
        A[w*LDP + r]  = Q[idx];
        Bm[w*LDP + r] = V[idx];
    }
    __syncthreads();

    const int ti = tid >> 4;   // rows h = ti*8 + r
    const int tj = tid & 15;   // cols g = tj*8 + 2*cp{,+1}

    unsigned long long acc[8][4];
    #pragma unroll
    for (int r = 0; r < 8; r++)
        #pragma unroll
        for (int c = 0; c < 4; c++) acc[r][c] = 0ull;

    // Phase A: S = Q @ V^T
    #pragma unroll 2
    for (int k = 0; k < 128; k++) {
        float4 q0 = *(const float4*)&A[k*LDP + ti*8];
        float4 q1 = *(const float4*)&A[k*LDP + ti*8 + 4];
        ulonglong2 v01 = *(const ulonglong2*)&Bm[k*LDP + tj*8];
        ulonglong2 v23 = *(const ulonglong2*)&Bm[k*LDP + tj*8 + 4];
        unsigned long long vb[4] = {v01.x, v01.y, v23.x, v23.y};
        float qa[8] = {q0.x, q0.y, q0.z, q0.w, q1.x, q1.y, q1.z, q1.w};
        #pragma unroll
        for (int r = 0; r < 8; r++) {
            unsigned long long qq = pack2(qa[r], qa[r]);
            #pragma unroll
            for (int c = 0; c < 4; c++)
                acc[r][c] = fma2(qq, vb[c], acc[r][c]);
        }
    }

    // unpack scores, softmax over g (reduce across 16 tj lanes)
    float s8[8][8];
    #pragma unroll
    for (int r = 0; r < 8; r++)
        #pragma unroll
        for (int c = 0; c < 4; c++)
            unpack2(acc[r][c], s8[r][2*c], s8[r][2*c+1]);

    float inv[8];
    #pragma unroll
    for (int r = 0; r < 8; r++) {
        float m = s8[r][0];
        #pragma unroll
        for (int c = 1; c < 8; c++) m = fmaxf(m, s8[r][c]);
        #pragma unroll
        for (int off = 1; off < 16; off <<= 1)
            m = fmaxf(m, __shfl_xor_sync(0xFFFFFFFFu, m, off));
        float s = 0.0f;
        #pragma unroll
        for (int c = 0; c < 8; c++) {
            float p = __expf(s8[r][c] - m);
            s8[r][c] = p;
            s += p;
        }
        #pragma unroll
        for (int off = 1; off < 16; off <<= 1)
            s += __shfl_xor_sync(0xFFFFFFFFu, s, off);
        inv[r] = 1.0f / s;
    }

    __syncthreads();

    // P row-major into A; K row-major into Bm
    #pragma unroll
    for (int r = 0; r < 8; r++) {
        int h = ti*8 + r;
        *(float4*)&A[h*LDP + tj*8]     = make_float4(s8[r][0], s8[r][1], s8[r][2], s8[r][3]);
        *(float4*)&A[h*LDP + tj*8 + 4] = make_float4(s8[r][4], s8[r][5], s8[r][6], s8[r][7]);
    }
    for (int idx = tid; idx < HW_; idx += 256) {
        int g = idx >> 7, w = idx & 127;
        Bm[g*LDP + w] = K[idx];
    }
    __syncthreads();

    // Phase C: ctx = P @ K
    unsigned long long oac[8][4];
    #pragma unroll
    for (int r = 0; r < 8; r++)
        #pragma unroll
        for (int c = 0; c < 4; c++) oac[r][c] = 0ull;

    #pragma unroll 2
    for (int k = 0; k < 128; k++) {
        ulonglong2 k01 = *(const ulonglong2*)&Bm[k*LDP + tj*8];
        ulonglong2 k23 = *(const ulonglong2*)&Bm[k*LDP + tj*8 + 4];
        unsigned long long kb[4] = {k01.x, k01.y, k23.x, k23.y};
        #pragma unroll
        for (int r = 0; r < 8; r++) {
            float a = A[(ti*8 + r)*LDP + k];
            unsigned long long ap = pack2(a, a);
            #pragma unroll
            for (int c = 0; c < 4; c++)
                oac[r][c] = fma2(ap, kb[c], oac[r][c]);
        }
    }

    #pragma unroll
    for (int r = 0; r < 8; r++) {
        int h = ti*8 + r;
        float iv = inv[r];
        float o8[8];
        #pragma unroll
        for (int c = 0; c < 4; c++)
            unpack2(oac[r][c], o8[2*c], o8[2*c+1]);
        int gb = n*HW_ + h*128 + tj*8;
        *(float4*)&out[gb]     = make_float4(o8[0]*iv, o8[1]*iv, o8[2]*iv, o8[3]*iv);
        *(float4*)&out[gb + 4] = make_float4(o8[4]*iv, o8[5]*iv, o8[6]*iv, o8[7]*iv);
    }
}

// ---------------------------------------------------------------------------
extern "C" void kernel_launch(void* const* d_in, const int* in_sizes, int n_in,
                              void* d_out, int out_size)
{
    const float* x  = (const float*)d_in[0];
    const float* e  = (const float*)d_in[1];
    const float* W1 = (const float*)d_in[2];
    const float* b1 = (const float*)d_in[3];
    const float* W2 = (const float*)d_in[4];
    const float* b2 = (const float*)d_in[5];
    const float* W3 = (const float*)d_in[6];
    const float* b3 = (const float*)d_in[7];
    float* out = (float*)d_out;

    const int smem1 = (64*128 + 16*128 + 64*68*2 + 16*68 + 3*64) * (int)sizeof(float);
    cudaFuncSetAttribute(qvk_kernel, cudaFuncAttributeMaxDynamicSharedMemorySize, smem1);
    qvk_kernel<<<dim3(128, 16), 256, smem1>>>(x, e, W1, b1, W2, b2, W3, b3);

    const int smem2 = 2 * 128 * LDP * (int)sizeof(float);
    cudaFuncSetAttribute(attn_kernel, cudaFuncAttributeMaxDynamicSharedMemorySize, smem2);
    attn_kernel<<<NTOT, 256, smem2>>>(out);
}

// round 3
// speedup vs baseline: 1.0389x; 1.0389x over previous
#include <cuda_runtime.h>

#define HW_ (128*128)
#define NTOT (16*64)

__device__ float g_Q[NTOT * HW_];
__device__ float g_V[NTOT * HW_];
__device__ float g_K[NTOT * HW_];

// ---- packed fp32x2 helpers ----
__device__ __forceinline__ unsigned long long pack2(float lo, float hi) {
    unsigned long long r;
    asm("mov.b64 %0, {%1, %2};" : "=l"(r) : "f"(lo), "f"(hi));
    return r;
}
__device__ __forceinline__ void unpack2(unsigned long long v, float& lo, float& hi) {
    asm("mov.b64 {%0, %1}, %2;" : "=f"(lo), "=f"(hi) : "l"(v));
}
__device__ __forceinline__ unsigned long long fma2(unsigned long long a,
                                                   unsigned long long b,
                                                   unsigned long long c) {
    unsigned long long d;
    asm("fma.rn.f32x2 %0, %1, %2, %3;" : "=l"(d) : "l"(a), "l"(b), "l"(c));
    return d;
}

// ---------------------------------------------------------------------------
// Kernel 1: fused 1x1-conv projections (R1 scalar version — measured faster).
// ---------------------------------------------------------------------------
__global__ __launch_bounds__(256) void qvk_kernel(
    const float* __restrict__ x, const float* __restrict__ e,
    const float* __restrict__ W1, const float* __restrict__ b1,
    const float* __restrict__ W2, const float* __restrict__ b2,
    const float* __restrict__ W3, const float* __restrict__ b3)
{
    extern __shared__ float sm[];
    float* Xs  = sm;               // [64][128]
    float* Es  = Xs + 64*128;      // [16][128]
    float* W2s = Es + 16*128;      // [64][68]
    float* W3s = W2s + 64*68;
    float* W1s = W3s + 64*68;      // [16][68]
    float* b1s = W1s + 16*68;
    float* b2s = b1s + 64;
    float* b3s = b2s + 64;

    const int tid = threadIdx.x;
    const int b   = blockIdx.y;
    const int p0  = blockIdx.x * 128;

    for (int idx = tid; idx < 4096; idx += 256) {
        int o = idx >> 6, c = idx & 63;
        W2s[c*68 + o] = W2[idx];
        W3s[c*68 + o] = W3[idx];
    }
    for (int idx = tid; idx < 1024; idx += 256) {
        int o = idx >> 4, c = idx & 15;
        W1s[c*68 + o] = W1[idx];
    }
    if (tid < 64) { b1s[tid] = b1[tid]; b2s[tid] = b2[tid]; b3s[tid] = b3[tid]; }

    for (int idx = tid; idx < 64*128; idx += 256) {
        int c = idx >> 7, p = idx & 127;
        Xs[idx] = x[(b*64 + c)*HW_ + p0 + p];
    }
    for (int idx = tid; idx < 16*128; idx += 256) {
        int c = idx >> 7, p = idx & 127;
        Es[idx] = e[(b*16 + c)*HW_ + p0 + p];
    }
    __syncthreads();

    const int oi = tid >> 4;
    const int pj = tid & 15;

    float accQ[4][8], accV[4][8], accK[4][8];
    #pragma unroll
    for (int i = 0; i < 4; i++) {
        float bq = b1s[oi*4+i], bv = b2s[oi*4+i], bk = b3s[oi*4+i];
        #pragma unroll
        for (int j = 0; j < 8; j++) { accQ[i][j] = bq; accV[i][j] = bv; accK[i][j] = bk; }
    }

    #pragma unroll 4
    for (int c = 0; c < 64; c++) {
        float4 a2v = *(const float4*)&W2s[c*68 + oi*4];
        float4 a3v = *(const float4*)&W3s[c*68 + oi*4];
        float4 x0  = *(const float4*)&Xs[c*128 + pj*8];
        float4 x1  = *(const float4*)&Xs[c*128 + pj*8 + 4];
        float av2[4] = {a2v.x, a2v.y, a2v.z, a2v.w};
        float av3[4] = {a3v.x, a3v.y, a3v.z, a3v.w};
        float xv[8]  = {x0.x, x0.y, x0.z, x0.w, x1.x, x1.y, x1.z, x1.w};
        #pragma unroll
        for (int i = 0; i < 4; i++)
            #pragma unroll
            for (int j = 0; j < 8; j++) {
                accV[i][j] += av2[i] * xv[j];
                accK[i][j] += av3[i] * xv[j];
            }
    }
    #pragma unroll 4
    for (int c = 0; c < 16; c++) {
        float4 a1v = *(const float4*)&W1s[c*68 + oi*4];
        float4 e0  = *(const float4*)&Es[c*128 + pj*8];
        float4 e1  = *(const float4*)&Es[c*128 + pj*8 + 4];
        float av1[4] = {a1v.x, a1v.y, a1v.z, a1v.w};
        float ev[8]  = {e0.x, e0.y, e0.z, e0.w, e1.x, e1.y, e1.z, e1.w};
        #pragma unroll
        for (int i = 0; i < 4; i++)
            #pragma unroll
            for (int j = 0; j < 8; j++)
                accQ[i][j] += av1[i] * ev[j];
    }

    #pragma unroll
    for (int i = 0; i < 4; i++) {
        int o  = oi*4 + i;
        int gb = (b*64 + o)*HW_ + p0 + pj*8;
        *(float4*)&g_Q[gb]     = make_float4(accQ[i][0], accQ[i][1], accQ[i][2], accQ[i][3]);
        *(float4*)&g_Q[gb + 4] = make_float4(accQ[i][4], accQ[i][5], accQ[i][6], accQ[i][7]);
        *(float4*)&g_V[gb]     = make_float4(accV[i][0], accV[i][1], accV[i][2], accV[i][3]);
        *(float4*)&g_V[gb + 4] = make_float4(accV[i][4], accV[i][5], accV[i][6], accV[i][7]);
        *(float4*)&g_K[gb]     = make_float4(accK[i][0], accK[i][1], accK[i][2], accK[i][3]);
        *(float4*)&g_K[gb + 4] = make_float4(accK[i][4], accK[i][5], accK[i][6], accK[i][7]);
    }
}

// ---------------------------------------------------------------------------
// Kernel 2: per-head attention, 512 threads (16 warps), 4x8 tile/thread.
// ---------------------------------------------------------------------------
#define LDP 132

__global__ __launch_bounds__(512) void attn_kernel(float* __restrict__ out)
{
    extern __shared__ float sm[];
    float* A  = sm;              // Q^T[w][h] -> later P[h][g]
    float* Bm = sm + 128*LDP;    // V^T[w][g] -> later K[g][w]

    const int tid = threadIdx.x;
    const int n   = blockIdx.x;
    const float* Q = g_Q + n*HW_;
    const float* V = g_V + n*HW_;
    const float* K = g_K + n*HW_;

    for (int idx = tid; idx < HW_; idx += 512) {
        int r = idx >> 7, w = idx & 127;
        A[w*LDP + r]  = Q[idx];
        Bm[w*LDP + r] = V[idx];
    }
    __syncthreads();

    const int ti = tid >> 4;   // 0..31 -> rows h = ti*4 + r
    const int tj = tid & 15;   // cols g = tj*8 + 2*cp{,+1}

    unsigned long long acc[4][4];
    #pragma unroll
    for (int r = 0; r < 4; r++)
        #pragma unroll
        for (int c = 0; c < 4; c++) acc[r][c] = 0ull;

    // Phase A: S = Q @ V^T
    #pragma unroll 4
    for (int k = 0; k < 128; k++) {
        float4 q0 = *(const float4*)&A[k*LDP + ti*4];
        ulonglong2 v01 = *(const ulonglong2*)&Bm[k*LDP + tj*8];
        ulonglong2 v23 = *(const ulonglong2*)&Bm[k*LDP + tj*8 + 4];
        unsigned long long vb[4] = {v01.x, v01.y, v23.x, v23.y};
        float qa[4] = {q0.x, q0.y, q0.z, q0.w};
        #pragma unroll
        for (int r = 0; r < 4; r++) {
            unsigned long long qq = pack2(qa[r], qa[r]);
            #pragma unroll
            for (int c = 0; c < 4; c++)
                acc[r][c] = fma2(qq, vb[c], acc[r][c]);
        }
    }

    // unpack, softmax over g (reduce across the 16 tj lanes = lower 4 lane bits)
    float s8[4][8];
    #pragma unroll
    for (int r = 0; r < 4; r++)
        #pragma unroll
        for (int c = 0; c < 4; c++)
            unpack2(acc[r][c], s8[r][2*c], s8[r][2*c+1]);

    float inv[4];
    #pragma unroll
    for (int r = 0; r < 4; r++) {
        float m = s8[r][0];
        #pragma unroll
        for (int c = 1; c < 8; c++) m = fmaxf(m, s8[r][c]);
        #pragma unroll
        for (int off = 1; off < 16; off <<= 1)
            m = fmaxf(m, __shfl_xor_sync(0xFFFFFFFFu, m, off));
        float s = 0.0f;
        #pragma unroll
        for (int c = 0; c < 8; c++) {
            float p = __expf(s8[r][c] - m);
            s8[r][c] = p;
            s += p;
        }
        #pragma unroll
        for (int off = 1; off < 16; off <<= 1)
            s += __shfl_xor_sync(0xFFFFFFFFu, s, off);
        inv[r] = 1.0f / s;
    }

    __syncthreads();

    // P row-major into A; K row-major into Bm
    #pragma unroll
    for (int r = 0; r < 4; r++) {
        int h = ti*4 + r;
        *(float4*)&A[h*LDP + tj*8]     = make_float4(s8[r][0], s8[r][1], s8[r][2], s8[r][3]);
        *(float4*)&A[h*LDP + tj*8 + 4] = make_float4(s8[r][4], s8[r][5], s8[r][6], s8[r][7]);
    }
    for (int idx = tid; idx < HW_; idx += 512) {
        int g = idx >> 7, w = idx & 127;
        Bm[g*LDP + w] = K[idx];
    }
    __syncthreads();

    // Phase C: ctx = P @ K
    unsigned long long oac[4][4];
    #pragma unroll
    for (int r = 0; r < 4; r++)
        #pragma unroll
        for (int c = 0; c < 4; c++) oac[r][c] = 0ull;

    #pragma unroll 4
    for (int k = 0; k < 128; k++) {
        ulonglong2 k01 = *(const ulonglong2*)&Bm[k*LDP + tj*8];
        ulonglong2 k23 = *(const ulonglong2*)&Bm[k*LDP + tj*8 + 4];
        unsigned long long kb[4] = {k01.x, k01.y, k23.x, k23.y};
        #pragma unroll
        for (int r = 0; r < 4; r++) {
            float a = A[(ti*4 + r)*LDP + k];
            unsigned long long ap = pack2(a, a);
            #pragma unroll
            for (int c = 0; c < 4; c++)
                oac[r][c] = fma2(ap, kb[c], oac[r][c]);
        }
    }

    #pragma unroll
    for (int r = 0; r < 4; r++) {
        int h = ti*4 + r;
        float iv = inv[r];
        float o8[8];
        #pragma unroll
        for (int c = 0; c < 4; c++)
            unpack2(oac[r][c], o8[2*c], o8[2*c+1]);
        int gb = n*HW_ + h*128 + tj*8;
        *(float4*)&out[gb]     = make_float4(o8[0]*iv, o8[1]*iv, o8[2]*iv, o8[3]*iv);
        *(float4*)&out[gb + 4] = make_float4(o8[4]*iv, o8[5]*iv, o8[6]*iv, o8[7]*iv);
    }
}

// ---------------------------------------------------------------------------
extern "C" void kernel_launch(void* const* d_in, const int* in_sizes, int n_in,
                              void* d_out, int out_size)
{
    const float* x  = (const float*)d_in[0];
    const float* e  = (const float*)d_in[1];
    const float* W1 = (const float*)d_in[2];
    const float* b1 = (const float*)d_in[3];
    const float* W2 = (const float*)d_in[4];
    const float* b2 = (const float*)d_in[5];
    const float* W3 = (const float*)d_in[6];
    const float* b3 = (const float*)d_in[7];
    float* out = (float*)d_out;

    const int smem1 = (64*128 + 16*128 + 64*68*2 + 16*68 + 3*64) * (int)sizeof(float);
    cudaFuncSetAttribute(qvk_kernel, cudaFuncAttributeMaxDynamicSharedMemorySize, smem1);
    qvk_kernel<<<dim3(128, 16), 256, smem1>>>(x, e, W1, b1, W2, b2, W3, b3);

    const int smem2 = 2 * 128 * LDP * (int)sizeof(float);
    cudaFuncSetAttribute(attn_kernel, cudaFuncAttributeMaxDynamicSharedMemorySize, smem2);
    attn_kernel<<<NTOT, 512, smem2>>>(out);
}

// round 4
// speedup vs baseline: 1.3388x; 1.2887x over previous
#include <cuda_runtime.h>
#include <cstdint>

#define HW_ (128*128)
#define NTOT (16*64)

__device__ float g_Q[NTOT * HW_];
__device__ float g_V[NTOT * HW_];
__device__ float g_K[NTOT * HW_];

// ---------------------------------------------------------------------------
// Kernel 1: fused 1x1-conv projections (R1 scalar version — measured fastest).
// ---------------------------------------------------------------------------
__global__ __launch_bounds__(256) void qvk_kernel(
    const float* __restrict__ x, const float* __restrict__ e,
    const float* __restrict__ W1, const float* __restrict__ b1,
    const float* __restrict__ W2, const float* __restrict__ b2,
    const float* __restrict__ W3, const float* __restrict__ b3)
{
    extern __shared__ float sm[];
    float* Xs  = sm;               // [64][128]
    float* Es  = Xs + 64*128;      // [16][128]
    float* W2s = Es + 16*128;      // [64][68]
    float* W3s = W2s + 64*68;
    float* W1s = W3s + 64*68;      // [16][68]
    float* b1s = W1s + 16*68;
    float* b2s = b1s + 64;
    float* b3s = b2s + 64;

    const int tid = threadIdx.x;
    const int b   = blockIdx.y;
    const int p0  = blockIdx.x * 128;

    for (int idx = tid; idx < 4096; idx += 256) {
        int o = idx >> 6, c = idx & 63;
        W2s[c*68 + o] = W2[idx];
        W3s[c*68 + o] = W3[idx];
    }
    for (int idx = tid; idx < 1024; idx += 256) {
        int o = idx >> 4, c = idx & 15;
        W1s[c*68 + o] = W1[idx];
    }
    if (tid < 64) { b1s[tid] = b1[tid]; b2s[tid] = b2[tid]; b3s[tid] = b3[tid]; }

    for (int idx = tid; idx < 64*128; idx += 256) {
        int c = idx >> 7, p = idx & 127;
        Xs[idx] = x[(b*64 + c)*HW_ + p0 + p];
    }
    for (int idx = tid; idx < 16*128; idx += 256) {
        int c = idx >> 7, p = idx & 127;
        Es[idx] = e[(b*16 + c)*HW_ + p0 + p];
    }
    __syncthreads();

    const int oi = tid >> 4;
    const int pj = tid & 15;

    float accQ[4][8], accV[4][8], accK[4][8];
    #pragma unroll
    for (int i = 0; i < 4; i++) {
        float bq = b1s[oi*4+i], bv = b2s[oi*4+i], bk = b3s[oi*4+i];
        #pragma unroll
        for (int j = 0; j < 8; j++) { accQ[i][j] = bq; accV[i][j] = bv; accK[i][j] = bk; }
    }

    #pragma unroll 4
    for (int c = 0; c < 64; c++) {
        float4 a2v = *(const float4*)&W2s[c*68 + oi*4];
        float4 a3v = *(const float4*)&W3s[c*68 + oi*4];
        float4 x0  = *(const float4*)&Xs[c*128 + pj*8];
        float4 x1  = *(const float4*)&Xs[c*128 + pj*8 + 4];
        float av2[4] = {a2v.x, a2v.y, a2v.z, a2v.w};
        float av3[4] = {a3v.x, a3v.y, a3v.z, a3v.w};
        float xv[8]  = {x0.x, x0.y, x0.z, x0.w, x1.x, x1.y, x1.z, x1.w};
        #pragma unroll
        for (int i = 0; i < 4; i++)
            #pragma unroll
            for (int j = 0; j < 8; j++) {
                accV[i][j] += av2[i] * xv[j];
                accK[i][j] += av3[i] * xv[j];
            }
    }
    #pragma unroll 4
    for (int c = 0; c < 16; c++) {
        float4 a1v = *(const float4*)&W1s[c*68 + oi*4];
        float4 e0  = *(const float4*)&Es[c*128 + pj*8];
        float4 e1  = *(const float4*)&Es[c*128 + pj*8 + 4];
        float av1[4] = {a1v.x, a1v.y, a1v.z, a1v.w};
        float ev[8]  = {e0.x, e0.y, e0.z, e0.w, e1.x, e1.y, e1.z, e1.w};
        #pragma unroll
        for (int i = 0; i < 4; i++)
            #pragma unroll
            for (int j = 0; j < 8; j++)
                accQ[i][j] += av1[i] * ev[j];
    }

    #pragma unroll
    for (int i = 0; i < 4; i++) {
        int o  = oi*4 + i;
        int gb = (b*64 + o)*HW_ + p0 + pj*8;
        *(float4*)&g_Q[gb]     = make_float4(accQ[i][0], accQ[i][1], accQ[i][2], accQ[i][3]);
        *(float4*)&g_Q[gb + 4] = make_float4(accQ[i][4], accQ[i][5], accQ[i][6], accQ[i][7]);
        *(float4*)&g_V[gb]     = make_float4(accV[i][0], accV[i][1], accV[i][2], accV[i][3]);
        *(float4*)&g_V[gb + 4] = make_float4(accV[i][4], accV[i][5], accV[i][6], accV[i][7]);
        *(float4*)&g_K[gb]     = make_float4(accK[i][0], accK[i][1], accK[i][2], accK[i][3]);
        *(float4*)&g_K[gb + 4] = make_float4(accK[i][4], accK[i][5], accK[i][6], accK[i][7]);
    }
}

// ---------------------------------------------------------------------------
// Kernel 2: per-head attention on tensor cores (tf32 mma, 3-term split).
// One CTA (8 warps, 256 thr) per head. Warp w owns output rows [w*16, w*16+16).
// ---------------------------------------------------------------------------
#define LDA 132

__device__ __forceinline__ void mma_tf32(float c[4], const uint32_t a[4],
                                         const uint32_t b0, const uint32_t b1) {
    asm volatile(
        "mma.sync.aligned.m16n8k8.row.col.f32.tf32.tf32.f32 "
        "{%0,%1,%2,%3}, {%4,%5,%6,%7}, {%8,%9}, {%0,%1,%2,%3};"
        : "+f"(c[0]), "+f"(c[1]), "+f"(c[2]), "+f"(c[3])
        : "r"(a[0]), "r"(a[1]), "r"(a[2]), "r"(a[3]), "r"(b0), "r"(b1));
}

// split x into tf32 hi (13 mantissa bits masked off) and tf32 lo
__device__ __forceinline__ void tf32_split(float x, uint32_t& hi, uint32_t& lo) {
    hi = __float_as_uint(x) & 0xffffe000u;
    float r = x - __uint_as_float(hi);
    lo = __float_as_uint(r) & 0xffffe000u;
}

__global__ __launch_bounds__(256) void attn_kernel(float* __restrict__ out)
{
    extern __shared__ float sm[];
    float* A  = sm;              // Q[h][w] -> later P[h][g]
    float* Bm = sm + 128*LDA;    // V[g][w] -> later K[g][w]

    const int tid  = threadIdx.x;
    const int warp = tid >> 5;
    const int lane = tid & 31;
    const int n    = blockIdx.x;
    const float* Q = g_Q + n*HW_;
    const float* V = g_V + n*HW_;
    const float* K = g_K + n*HW_;

    // Stage Q, V (no transpose; row stride LDA)
    for (int idx = tid; idx < 128*32; idx += 256) {
        int row = idx >> 5, c4 = (idx & 31) * 4;
        *(float4*)&A[row*LDA + c4]  = *(const float4*)&Q[row*128 + c4];
        *(float4*)&Bm[row*LDA + c4] = *(const float4*)&V[row*128 + c4];
    }
    __syncthreads();

    const int g4 = lane >> 2;        // 0..7
    const int tg = lane & 3;         // 0..3
    const int r0 = warp*16 + g4;     // rows r0 (c0/c1) and r0+8 (c2/c3)

    float acc[16][4];
    #pragma unroll
    for (int nt = 0; nt < 16; nt++)
        #pragma unroll
        for (int i = 0; i < 4; i++) acc[nt][i] = 0.0f;

    // ---- Phase A: S = Q @ V^T.  A[m][k]=A[m*LDA+k], B[k][nn]=Bm[nn*LDA+k]
    #pragma unroll 1
    for (int k = 0; k < 16; k++) {
        const int kb = k*8 + tg;
        uint32_t ah[4], al[4];
        tf32_split(A[r0*LDA + kb],           ah[0], al[0]);
        tf32_split(A[(r0+8)*LDA + kb],       ah[1], al[1]);
        tf32_split(A[r0*LDA + kb + 4],       ah[2], al[2]);
        tf32_split(A[(r0+8)*LDA + kb + 4],   ah[3], al[3]);
        #pragma unroll
        for (int nt = 0; nt < 16; nt++) {
            const int gc = nt*8 + g4;
            uint32_t bh0, bl0, bh1, bl1;
            tf32_split(Bm[gc*LDA + kb],     bh0, bl0);
            tf32_split(Bm[gc*LDA + kb + 4], bh1, bl1);
            mma_tf32(acc[nt], ah, bh0, bh1);
            mma_tf32(acc[nt], al, bh0, bh1);
            mma_tf32(acc[nt], ah, bl0, bl1);
        }
    }

    // ---- Softmax over columns. Rows r0, r0+8 live in this thread-quad.
    float m1 = -1e30f, m2 = -1e30f;
    #pragma unroll
    for (int nt = 0; nt < 16; nt++) {
        m1 = fmaxf(m1, fmaxf(acc[nt][0], acc[nt][1]));
        m2 = fmaxf(m2, fmaxf(acc[nt][2], acc[nt][3]));
    }
    #pragma unroll
    for (int off = 1; off < 4; off <<= 1) {
        m1 = fmaxf(m1, __shfl_xor_sync(0xFFFFFFFFu, m1, off));
        m2 = fmaxf(m2, __shfl_xor_sync(0xFFFFFFFFu, m2, off));
    }
    float s1 = 0.0f, s2 = 0.0f;
    #pragma unroll
    for (int nt = 0; nt < 16; nt++) {
        acc[nt][0] = __expf(acc[nt][0] - m1);
        acc[nt][1] = __expf(acc[nt][1] - m1);
        acc[nt][2] = __expf(acc[nt][2] - m2);
        acc[nt][3] = __expf(acc[nt][3] - m2);
        s1 += acc[nt][0] + acc[nt][1];
        s2 += acc[nt][2] + acc[nt][3];
    }
    #pragma unroll
    for (int off = 1; off < 4; off <<= 1) {
        s1 += __shfl_xor_sync(0xFFFFFFFFu, s1, off);
        s2 += __shfl_xor_sync(0xFFFFFFFFu, s2, off);
    }
    const float inv1 = 1.0f / s1, inv2 = 1.0f / s2;

    // Store unnormalized P into A (own 16-row band only)
    #pragma unroll
    for (int nt = 0; nt < 16; nt++) {
        *(float2*)&A[r0*LDA     + nt*8 + 2*tg] = make_float2(acc[nt][0], acc[nt][1]);
        *(float2*)&A[(r0+8)*LDA + nt*8 + 2*tg] = make_float2(acc[nt][2], acc[nt][3]);
    }
    __syncthreads();   // all warps done reading V from Bm & writing P

    // Load K into Bm
    for (int idx = tid; idx < 128*32; idx += 256) {
        int row = idx >> 5, c4 = (idx & 31) * 4;
        *(float4*)&Bm[row*LDA + c4] = *(const float4*)&K[row*128 + c4];
    }
    __syncthreads();

    // ---- Phase C: ctx = P @ K.  B[k][nn] = Bm[k*LDA + nn]  (k-major)
    float oac[16][4];
    #pragma unroll
    for (int nt = 0; nt < 16; nt++)
        #pragma unroll
        for (int i = 0; i < 4; i++) oac[nt][i] = 0.0f;

    #pragma unroll 1
    for (int k = 0; k < 16; k++) {
        const int kb = k*8 + tg;
        uint32_t ah[4], al[4];
        tf32_split(A[r0*LDA + kb],           ah[0], al[0]);
        tf32_split(A[(r0+8)*LDA + kb],       ah[1], al[1]);
        tf32_split(A[r0*LDA + kb + 4],       ah[2], al[2]);
        tf32_split(A[(r0+8)*LDA + kb + 4],   ah[3], al[3]);
        #pragma unroll
        for (int nt = 0; nt < 16; nt++) {
            const int nc = nt*8 + g4;
            uint32_t bh0, bl0, bh1, bl1;
            tf32_split(Bm[kb*LDA + nc],       bh0, bl0);
            tf32_split(Bm[(kb+4)*LDA + nc],   bh1, bl1);
            mma_tf32(oac[nt], ah, bh0, bh1);
            mma_tf32(oac[nt], al, bh0, bh1);
            mma_tf32(oac[nt], ah, bl0, bl1);
        }
    }

    // Epilogue: scale rows by 1/rowsum, write out
    #pragma unroll
    for (int nt = 0; nt < 16; nt++) {
        int cbase = nt*8 + 2*tg;
        *(float2*)&out[n*HW_ + r0*128 + cbase] =
            make_float2(oac[nt][0]*inv1, oac[nt][1]*inv1);
        *(float2*)&out[n*HW_ + (r0+8)*128 + cbase] =
            make_float2(oac[nt][2]*inv2, oac[nt][3]*inv2);
    }
}

// ---------------------------------------------------------------------------
extern "C" void kernel_launch(void* const* d_in, const int* in_sizes, int n_in,
                              void* d_out, int out_size)
{
    const float* x  = (const float*)d_in[0];
    const float* e  = (const float*)d_in[1];
    const float* W1 = (const float*)d_in[2];
    const float* b1 = (const float*)d_in[3];
    const float* W2 = (const float*)d_in[4];
    const float* b2 = (const float*)d_in[5];
    const float* W3 = (const float*)d_in[6];
    const float* b3 = (const float*)d_in[7];
    float* out = (float*)d_out;

    const int smem1 = (64*128 + 16*128 + 64*68*2 + 16*68 + 3*64) * (int)sizeof(float);
    cudaFuncSetAttribute(qvk_kernel, cudaFuncAttributeMaxDynamicSharedMemorySize, smem1);
    qvk_kernel<<<dim3(128, 16), 256, smem1>>>(x, e, W1, b1, W2, b2, W3, b3);

    const int smem2 = 2 * 128 * LDA * (int)sizeof(float);
    cudaFuncSetAttribute(attn_kernel, cudaFuncAttributeMaxDynamicSharedMemorySize, smem2);
    attn_kernel<<<NTOT, 256, smem2>>>(out);
}